// round 1
// baseline (speedup 1.0000x reference)
#include <cuda_runtime.h>
#include <cuda_bf16.h>
#include <math.h>

// Problem constants
#define BSZ   4
#define SEQ   2048
#define DIM   1024
#define OUTD  1024

// Scratch: Q|K|V stacked [3][B*S][OUT], and the attention score matrix [B][S][S].
// __device__ globals (allocation-free per harness rules).
__device__ float g_qkv[3ull * BSZ * SEQ * OUTD];   // 96 MB
__device__ float g_scores[(size_t)BSZ * SEQ * SEQ]; // 64 MB

// ---------------------------------------------------------------------------
// Tiled SGEMM: C = alpha * A * op(B)
//   A: [M,K] row-major
//   B: [K,N] row-major (TRANS_B=false)  or  [N,K] row-major (TRANS_B=true, computes A*B^T)
//   C: [M,N] row-major
// Batched over blockIdx.z with element strides. All dims assumed multiples of tile sizes.
// Tile: 128x128x8, 256 threads, 8x8 per thread, float4 global loads.
// ---------------------------------------------------------------------------
#define BM 128
#define BN 128
#define BKK 8
#define TM 8
#define TN 8

template <bool TRANS_B>
__global__ __launch_bounds__(256) void sgemm_batched(
    const float* __restrict__ A, const float* __restrict__ B, float* __restrict__ C,
    int M, int N, int K,
    long strideA, long strideB, long strideC,
    float alpha)
{
    __shared__ float As[BKK][BM];
    __shared__ float Bs[BKK][BN];

    const float* Ab = A + (size_t)blockIdx.z * strideA;
    const float* Bb = B + (size_t)blockIdx.z * strideB;
    float*       Cb = C + (size_t)blockIdx.z * strideC;

    const int tid  = threadIdx.x;          // 0..255
    const int cRow = blockIdx.y * BM;
    const int cCol = blockIdx.x * BN;

    const int tx = tid & 15;               // 0..15 (col group)
    const int ty = tid >> 4;               // 0..15 (row group)

    // A-tile load mapping: 128 rows x 8 cols -> 256 threads x float4
    const int aRow = tid >> 1;             // 0..127
    const int aCol = (tid & 1) * 4;        // 0 or 4

    float acc[TM][TN];
    #pragma unroll
    for (int i = 0; i < TM; i++)
        #pragma unroll
        for (int j = 0; j < TN; j++)
            acc[i][j] = 0.0f;

    for (int kb = 0; kb < K; kb += BKK) {
        // Load A tile (transposed into As[k][m])
        float4 av = *reinterpret_cast<const float4*>(
            &Ab[(size_t)(cRow + aRow) * K + kb + aCol]);
        As[aCol + 0][aRow] = av.x;
        As[aCol + 1][aRow] = av.y;
        As[aCol + 2][aRow] = av.z;
        As[aCol + 3][aRow] = av.w;

        if (!TRANS_B) {
            // B tile: 8 rows x 128 cols
            const int bRow = tid >> 5;          // 0..7
            const int bCol = (tid & 31) * 4;    // 0..124
            float4 bv = *reinterpret_cast<const float4*>(
                &Bb[(size_t)(kb + bRow) * N + cCol + bCol]);
            *reinterpret_cast<float4*>(&Bs[bRow][bCol]) = bv;
        } else {
            // B is [N,K]; tile: Bs[k][n] = B[cCol+n][kb+k]
            const int bRow = tid >> 1;          // n offset 0..127
            const int bCol = (tid & 1) * 4;     // k offset 0 or 4
            float4 bv = *reinterpret_cast<const float4*>(
                &Bb[(size_t)(cCol + bRow) * K + kb + bCol]);
            Bs[bCol + 0][bRow] = bv.x;
            Bs[bCol + 1][bRow] = bv.y;
            Bs[bCol + 2][bRow] = bv.z;
            Bs[bCol + 3][bRow] = bv.w;
        }
        __syncthreads();

        #pragma unroll
        for (int k = 0; k < BKK; k++) {
            float ar[TM], br[TN];
            float4 a0 = *reinterpret_cast<const float4*>(&As[k][ty * TM]);
            float4 a1 = *reinterpret_cast<const float4*>(&As[k][ty * TM + 4]);
            ar[0]=a0.x; ar[1]=a0.y; ar[2]=a0.z; ar[3]=a0.w;
            ar[4]=a1.x; ar[5]=a1.y; ar[6]=a1.z; ar[7]=a1.w;
            float4 b0 = *reinterpret_cast<const float4*>(&Bs[k][tx * TN]);
            float4 b1 = *reinterpret_cast<const float4*>(&Bs[k][tx * TN + 4]);
            br[0]=b0.x; br[1]=b0.y; br[2]=b0.z; br[3]=b0.w;
            br[4]=b1.x; br[5]=b1.y; br[6]=b1.z; br[7]=b1.w;
            #pragma unroll
            for (int i = 0; i < TM; i++)
                #pragma unroll
                for (int j = 0; j < TN; j++)
                    acc[i][j] = fmaf(ar[i], br[j], acc[i][j]);
        }
        __syncthreads();
    }

    // Write back (two float4 per row of the 8x8 microtile)
    #pragma unroll
    for (int i = 0; i < TM; i++) {
        float4 o0, o1;
        o0.x = alpha * acc[i][0]; o0.y = alpha * acc[i][1];
        o0.z = alpha * acc[i][2]; o0.w = alpha * acc[i][3];
        o1.x = alpha * acc[i][4]; o1.y = alpha * acc[i][5];
        o1.z = alpha * acc[i][6]; o1.w = alpha * acc[i][7];
        float* cptr = &Cb[(size_t)(cRow + ty * TM + i) * N + cCol + tx * TN];
        *reinterpret_cast<float4*>(cptr)     = o0;
        *reinterpret_cast<float4*>(cptr + 4) = o1;
    }
}

// ---------------------------------------------------------------------------
// Row softmax over rows of length 2048. One block (256 threads) per row.
// ---------------------------------------------------------------------------
__device__ __forceinline__ float warpReduceMax(float v) {
    #pragma unroll
    for (int o = 16; o > 0; o >>= 1) v = fmaxf(v, __shfl_xor_sync(0xffffffffu, v, o));
    return v;
}
__device__ __forceinline__ float warpReduceSum(float v) {
    #pragma unroll
    for (int o = 16; o > 0; o >>= 1) v += __shfl_xor_sync(0xffffffffu, v, o);
    return v;
}

__global__ __launch_bounds__(256) void softmax_rows(float* __restrict__ S)
{
    const int t = threadIdx.x;
    float4* row = reinterpret_cast<float4*>(S + (size_t)blockIdx.x * SEQ);
    float4 a = row[t];
    float4 b = row[t + 256];

    __shared__ float red[8];

    // max
    float m = fmaxf(fmaxf(fmaxf(a.x, a.y), fmaxf(a.z, a.w)),
                    fmaxf(fmaxf(b.x, b.y), fmaxf(b.z, b.w)));
    m = warpReduceMax(m);
    if ((t & 31) == 0) red[t >> 5] = m;
    __syncthreads();
    if (t < 32) {
        float v = (t < 8) ? red[t] : -INFINITY;
        v = warpReduceMax(v);
        if (t == 0) red[0] = v;
    }
    __syncthreads();
    m = red[0];
    __syncthreads();

    // exp + sum
    a.x = expf(a.x - m); a.y = expf(a.y - m); a.z = expf(a.z - m); a.w = expf(a.w - m);
    b.x = expf(b.x - m); b.y = expf(b.y - m); b.z = expf(b.z - m); b.w = expf(b.w - m);
    float s = a.x + a.y + a.z + a.w + b.x + b.y + b.z + b.w;
    s = warpReduceSum(s);
    if ((t & 31) == 0) red[t >> 5] = s;
    __syncthreads();
    if (t < 32) {
        float v = (t < 8) ? red[t] : 0.0f;
        v = warpReduceSum(v);
        if (t == 0) red[0] = v;
    }
    __syncthreads();
    const float inv = 1.0f / red[0];

    a.x *= inv; a.y *= inv; a.z *= inv; a.w *= inv;
    b.x *= inv; b.y *= inv; b.z *= inv; b.w *= inv;
    row[t] = a;
    row[t + 256] = b;
}

// ---------------------------------------------------------------------------
// Launch
// ---------------------------------------------------------------------------
extern "C" void kernel_launch(void* const* d_in, const int* in_sizes, int n_in,
                              void* d_out, int out_size)
{
    const float* x = (const float*)d_in[0];   // [B,S,D]
    const float* y = (const float*)d_in[1];   // [B,S,D]
    const float* w = (const float*)d_in[2];   // [3,D,OUT]
    float* out = (float*)d_out;               // [B,S,OUT]

    float* qkv = nullptr;
    float* sc  = nullptr;
    cudaGetSymbolAddress((void**)&qkv, g_qkv);
    cudaGetSymbolAddress((void**)&sc,  g_scores);

    const long TOK   = (long)BSZ * SEQ;            // 8192
    const long QKVST = TOK * OUTD;                 // 8388608 (per Q/K/V plane)
    const long WST   = (long)DIM * OUTD;           // 1048576
    const long SST   = (long)SEQ * SEQ;            // 4194304
    const long BQKV  = (long)SEQ * OUTD;           // 2097152 (per-batch Q/K/V stride)

    dim3 blk(256);

    // Q = x @ W0, K = x @ W1   (z=2 batches share A=x, stride over W and C)
    sgemm_batched<false><<<dim3(OUTD / BN, TOK / BM, 2), blk>>>(
        x, w, qkv, (int)TOK, OUTD, DIM, 0, WST, QKVST, 1.0f);

    // V = y @ W2
    sgemm_batched<false><<<dim3(OUTD / BN, TOK / BM, 1), blk>>>(
        y, w + 2 * WST, qkv + 2 * QKVST, (int)TOK, OUTD, DIM, 0, 0, 0, 1.0f);

    // S = (Q @ K^T) * 1/sqrt(OUT), per batch
    sgemm_batched<true><<<dim3(SEQ / BN, SEQ / BM, BSZ), blk>>>(
        qkv, qkv + QKVST, sc, SEQ, SEQ, OUTD, BQKV, BQKV, SST, 0.03125f);

    // softmax rows
    softmax_rows<<<BSZ * SEQ, 256>>>(sc);

    // out = A @ V, per batch
    sgemm_batched<false><<<dim3(OUTD / BN, SEQ / BM, BSZ), blk>>>(
        sc, qkv + 2 * QKVST, out, SEQ, OUTD, SEQ, SST, BQKV, BQKV, 1.0f);
}

// round 4
// speedup vs baseline: 2.9892x; 2.9892x over previous
#include <cuda_runtime.h>
#include <cuda_bf16.h>
#include <cstdint>
#include <math.h>

// Problem constants
#define BSZ   4
#define SEQ   2048
#define DIM   1024
#define OUTD  1024

// Scratch (__device__ globals; allocation-free). 128B aligned for cp.async.
__device__ __align__(128) float g_qkv[3ull * BSZ * SEQ * OUTD];   // Q | K | V^T planes
__device__ __align__(128) float g_scores[(size_t)BSZ * SEQ * SEQ];
__device__ __align__(128) float g_xr[(size_t)BSZ * SEQ * DIM];
__device__ __align__(128) float g_yr[(size_t)BSZ * SEQ * DIM];
__device__ __align__(128) float g_wT[3ull * OUTD * DIM];

// ---------------------------------------------------------------------------
// Helpers
// ---------------------------------------------------------------------------
__device__ __forceinline__ uint32_t smem_u32(const void* p) {
    uint32_t a;
    asm("{ .reg .u64 t; cvta.to.shared.u64 t, %1; cvt.u32.u64 %0, t; }" : "=r"(a) : "l"(p));
    return a;
}
__device__ __forceinline__ float rn_tf32(float x) {
    uint32_t o;
    asm("cvt.rna.tf32.f32 %0, %1;" : "=r"(o) : "f"(x));
    return __uint_as_float(o);
}
__device__ __forceinline__ void cp16(uint32_t dst, const void* src) {
    asm volatile("cp.async.cg.shared.global [%0], [%1], 16;" :: "r"(dst), "l"(src) : "memory");
}
#define CP_COMMIT() asm volatile("cp.async.commit_group;" ::: "memory")
#define CP_WAIT1()  asm volatile("cp.async.wait_group 1;" ::: "memory")
#define CP_WAIT0()  asm volatile("cp.async.wait_group 0;" ::: "memory")

// m16n8k8 tf32 MMA (sm_80+; legal on plain sm_100 target)
__device__ __forceinline__ void mma_tf32(float* c, const uint32_t* a, const uint32_t* b) {
    asm volatile(
        "mma.sync.aligned.m16n8k8.row.col.f32.tf32.tf32.f32 "
        "{%0,%1,%2,%3}, {%4,%5,%6,%7}, {%8,%9}, {%0,%1,%2,%3};"
        : "+f"(c[0]), "+f"(c[1]), "+f"(c[2]), "+f"(c[3])
        : "r"(a[0]), "r"(a[1]), "r"(a[2]), "r"(a[3]), "r"(b[0]), "r"(b[1]));
}

// ---------------------------------------------------------------------------
// tf32 tensor GEMM: C = alpha * A * B^T
//   A: [M,K] row-major, B: [N,K] row-major, C: [M,N] row-major.
//   All operands pre-rounded to tf32 (low 13 mantissa bits zero).
// CTA tile 128x128, K-chunk 32, 256 threads (8 warps, 2x4, warp tile 64x32).
// SMEM rows padded to 36 floats -> conflict-free fragment LDS.
// ---------------------------------------------------------------------------
#define TK_ 32
#define LDA_ 36                          // padded row stride (floats)
#define TILE_F (128 * LDA_)              // floats per operand tile = 4608
#define STAGE_F (2 * TILE_F)             // A+B per stage
#define GEMM_SMEM (2 * STAGE_F * 4)      // 73728 bytes

template <bool ROUND, bool TRANSV>
__global__ __launch_bounds__(256) void gemm_tf32(
    const float* __restrict__ A, const float* __restrict__ B, float* __restrict__ C,
    int M, int N, int K, long sA, long sB, long sC, float alpha)
{
    extern __shared__ float sm[];
    const uint32_t sbase = smem_u32(sm);

    const int tid  = threadIdx.x;
    const int lane = tid & 31;
    const int wid  = tid >> 5;
    const int wr   = wid >> 2;            // warp row 0..1
    const int wc   = wid & 3;             // warp col 0..3
    const int m0   = wr * 64;
    const int n0   = wc * 32;
    const int fr   = lane >> 2;           // fragment row group 0..7
    const int fc   = lane & 3;            // fragment col group 0..3

    const float* Ab = A + (size_t)blockIdx.z * sA;
    const float* Bb = B + (size_t)blockIdx.z * sB;
    float*       Cb = C + (size_t)blockIdx.z * sC;
    const int cRow = blockIdx.y * 128;
    const int cCol = blockIdx.x * 128;

    float acc[4][4][4];
    #pragma unroll
    for (int i = 0; i < 4; i++)
        #pragma unroll
        for (int j = 0; j < 4; j++)
            #pragma unroll
            for (int v = 0; v < 4; v++) acc[i][j][v] = 0.0f;

    const int NT = K / TK_;

    // Tile loader: 128 rows x 8 x 16B chunks per operand; 4 chunks/thread/operand.
    auto loadTile = [&](int it, int s) {
        const uint32_t aB = sbase + (uint32_t)s * (STAGE_F * 4);
        const uint32_t bB = aB + TILE_F * 4;
        const float* Ag = Ab + (size_t)cRow * K + (size_t)it * TK_;
        const float* Bg = Bb + (size_t)cCol * K + (size_t)it * TK_;
        #pragma unroll
        for (int j = 0; j < 4; j++) {
            const int id = tid + j * 256;        // 0..1023
            const int r = id >> 3, c = id & 7;   // row, 16B chunk
            const uint32_t off = (uint32_t)r * (LDA_ * 4) + (uint32_t)c * 16;
            cp16(aB + off, Ag + (size_t)r * K + c * 4);
            cp16(bB + off, Bg + (size_t)r * K + c * 4);
        }
    };

    loadTile(0, 0);
    CP_COMMIT();

    for (int it = 0; it < NT; it++) {
        if (it + 1 < NT) {
            loadTile(it + 1, (it + 1) & 1);
            CP_COMMIT();
            CP_WAIT1();
        } else {
            CP_WAIT0();
        }
        __syncthreads();

        const float* Asm = sm + (it & 1) * STAGE_F;
        const float* Bsm = Asm + TILE_F;

        #pragma unroll
        for (int kk = 0; kk < 4; kk++) {
            const int k0 = kk * 8;
            uint32_t a[4][4], b[4][2];
            #pragma unroll
            for (int i = 0; i < 4; i++) {
                const float* ap = Asm + (size_t)(m0 + 16 * i + fr) * LDA_ + k0 + fc;
                a[i][0] = __float_as_uint(ap[0]);
                a[i][1] = __float_as_uint(ap[8 * LDA_]);
                a[i][2] = __float_as_uint(ap[4]);
                a[i][3] = __float_as_uint(ap[8 * LDA_ + 4]);
            }
            #pragma unroll
            for (int j = 0; j < 4; j++) {
                const float* bp = Bsm + (size_t)(n0 + 8 * j + fr) * LDA_ + k0 + fc;
                b[j][0] = __float_as_uint(bp[0]);
                b[j][1] = __float_as_uint(bp[4]);
            }
            #pragma unroll
            for (int i = 0; i < 4; i++)
                #pragma unroll
                for (int j = 0; j < 4; j++)
                    mma_tf32(acc[i][j], a[i], b[j]);
        }
        __syncthreads();
    }

    // Epilogue
    #pragma unroll
    for (int i = 0; i < 4; i++) {
        const int row0 = cRow + m0 + 16 * i + fr;
        #pragma unroll
        for (int j = 0; j < 4; j++) {
            const int col0 = cCol + n0 + 8 * j + 2 * fc;
            float v0 = alpha * acc[i][j][0];
            float v1 = alpha * acc[i][j][1];
            float v2 = alpha * acc[i][j][2];
            float v3 = alpha * acc[i][j][3];
            if (ROUND) { v0 = rn_tf32(v0); v1 = rn_tf32(v1);
                         v2 = rn_tf32(v2); v3 = rn_tf32(v3); }
            if (TRANSV) {
                // Store transposed: out[b][o][s], row -> (b, s), col -> o
                const int b_ = row0 >> 11, s_ = row0 & (SEQ - 1);
                float* o0 = C + (size_t)b_ * OUTD * SEQ + (size_t)col0 * SEQ + s_;
                o0[0]       = v0;
                o0[SEQ]     = v1;
                o0[8]       = v2;     // row0+8, col0
                o0[SEQ + 8] = v3;     // row0+8, col0+1
            } else {
                float2 p0 = make_float2(v0, v1);
                float2 p1 = make_float2(v2, v3);
                *reinterpret_cast<float2*>(Cb + (size_t)row0 * N + col0)       = p0;
                *reinterpret_cast<float2*>(Cb + (size_t)(row0 + 8) * N + col0) = p1;
            }
        }
    }
}

// ---------------------------------------------------------------------------
// Prep: round to tf32 (RN), batched over z (0: x->xr, 1: y->yr); transpose+round W
// ---------------------------------------------------------------------------
__global__ __launch_bounds__(256) void round_tf32_kernel(
    const float4* __restrict__ in0, float4* __restrict__ out0,
    const float4* __restrict__ in1, float4* __restrict__ out1, int n4)
{
    int i = blockIdx.x * 256 + threadIdx.x;
    const float4* in  = blockIdx.z ? in1  : in0;
    float4*       out = blockIdx.z ? out1 : out0;
    if (i < n4) {
        float4 v = in[i];
        v.x = rn_tf32(v.x); v.y = rn_tf32(v.y); v.z = rn_tf32(v.z); v.w = rn_tf32(v.w);
        out[i] = v;
    }
}

__global__ __launch_bounds__(256) void wtrans_kernel(
    const float* __restrict__ w, float* __restrict__ wT)
{
    __shared__ float t[32][33];
    const int p = blockIdx.z;
    const int o0 = blockIdx.x * 32, d0 = blockIdx.y * 32;
    const int tx = threadIdx.x & 31, ty = threadIdx.x >> 5;   // 32 x 8
    const float* wp = w + (size_t)p * DIM * OUTD;
    float* wtp = wT + (size_t)p * OUTD * DIM;
    #pragma unroll
    for (int j = 0; j < 4; j++)
        t[ty + j * 8][tx] = wp[(size_t)(d0 + ty + j * 8) * OUTD + o0 + tx];
    __syncthreads();
    #pragma unroll
    for (int j = 0; j < 4; j++)
        wtp[(size_t)(o0 + ty + j * 8) * DIM + d0 + tx] = rn_tf32(t[tx][ty + j * 8]);
}

// ---------------------------------------------------------------------------
// Row softmax (rows of 2048), output rounded to tf32
// ---------------------------------------------------------------------------
__device__ __forceinline__ float warpReduceMax(float v) {
    #pragma unroll
    for (int o = 16; o > 0; o >>= 1) v = fmaxf(v, __shfl_xor_sync(0xffffffffu, v, o));
    return v;
}
__device__ __forceinline__ float warpReduceSum(float v) {
    #pragma unroll
    for (int o = 16; o > 0; o >>= 1) v += __shfl_xor_sync(0xffffffffu, v, o);
    return v;
}

__global__ __launch_bounds__(256) void softmax_rows(float* __restrict__ S)
{
    const int t = threadIdx.x;
    float4* row = reinterpret_cast<float4*>(S + (size_t)blockIdx.x * SEQ);
    float4 a = row[t];
    float4 b = row[t + 256];

    __shared__ float red[8];

    float m = fmaxf(fmaxf(fmaxf(a.x, a.y), fmaxf(a.z, a.w)),
                    fmaxf(fmaxf(b.x, b.y), fmaxf(b.z, b.w)));
    m = warpReduceMax(m);
    if ((t & 31) == 0) red[t >> 5] = m;
    __syncthreads();
    if (t < 32) {
        float v = (t < 8) ? red[t] : -INFINITY;
        v = warpReduceMax(v);
        if (t == 0) red[0] = v;
    }
    __syncthreads();
    m = red[0];
    __syncthreads();

    a.x = expf(a.x - m); a.y = expf(a.y - m); a.z = expf(a.z - m); a.w = expf(a.w - m);
    b.x = expf(b.x - m); b.y = expf(b.y - m); b.z = expf(b.z - m); b.w = expf(b.w - m);
    float s = a.x + a.y + a.z + a.w + b.x + b.y + b.z + b.w;
    s = warpReduceSum(s);
    if ((t & 31) == 0) red[t >> 5] = s;
    __syncthreads();
    if (t < 32) {
        float v = (t < 8) ? red[t] : 0.0f;
        v = warpReduceSum(v);
        if (t == 0) red[0] = v;
    }
    __syncthreads();
    const float inv = 1.0f / red[0];

    a.x = rn_tf32(a.x * inv); a.y = rn_tf32(a.y * inv);
    a.z = rn_tf32(a.z * inv); a.w = rn_tf32(a.w * inv);
    b.x = rn_tf32(b.x * inv); b.y = rn_tf32(b.y * inv);
    b.z = rn_tf32(b.z * inv); b.w = rn_tf32(b.w * inv);
    row[t] = a;
    row[t + 256] = b;
}

// ---------------------------------------------------------------------------
// Launch
// ---------------------------------------------------------------------------
extern "C" void kernel_launch(void* const* d_in, const int* in_sizes, int n_in,
                              void* d_out, int out_size)
{
    const float* x = (const float*)d_in[0];   // [B,S,D]
    const float* y = (const float*)d_in[1];   // [B,S,D]
    const float* w = (const float*)d_in[2];   // [3,D,OUT]
    float* out = (float*)d_out;               // [B,S,OUT]

    float *qkv, *sc, *xr, *yr, *wT;
    cudaGetSymbolAddress((void**)&qkv, g_qkv);
    cudaGetSymbolAddress((void**)&sc,  g_scores);
    cudaGetSymbolAddress((void**)&xr,  g_xr);
    cudaGetSymbolAddress((void**)&yr,  g_yr);
    cudaGetSymbolAddress((void**)&wT,  g_wT);

    cudaFuncSetAttribute(gemm_tf32<true,  false>, cudaFuncAttributeMaxDynamicSharedMemorySize, GEMM_SMEM);
    cudaFuncSetAttribute(gemm_tf32<false, false>, cudaFuncAttributeMaxDynamicSharedMemorySize, GEMM_SMEM);
    cudaFuncSetAttribute(gemm_tf32<true,  true >, cudaFuncAttributeMaxDynamicSharedMemorySize, GEMM_SMEM);

    const long TOK   = (long)BSZ * SEQ;        // 8192
    const long QKVST = TOK * OUTD;             // per-plane
    const long WST   = (long)DIM * OUTD;
    const long SST   = (long)SEQ * SEQ;
    const long BQKV  = (long)SEQ * OUTD;

    // Prep: round inputs (x,y batched over z), transpose+round W
    const int n4 = (int)(TOK * DIM / 4);
    round_tf32_kernel<<<dim3((n4 + 255) / 256, 1, 2), 256>>>(
        (const float4*)x, (float4*)xr, (const float4*)y, (float4*)yr, n4);
    wtrans_kernel<<<dim3(OUTD / 32, DIM / 32, 3), 256>>>(w, wT);

    // Q = xr @ W0^T', K = xr @ W1^T'  (z over weight planes), rounded outputs
    gemm_tf32<true, false><<<dim3(OUTD / 128, TOK / 128, 2), 256, GEMM_SMEM>>>(
        xr, wT, qkv, (int)TOK, OUTD, DIM, 0, WST, QKVST, 1.0f);

    // V^T = (yr @ W2^T')^T  (transposed, rounded store into plane 2)
    gemm_tf32<true, true><<<dim3(OUTD / 128, TOK / 128, 1), 256, GEMM_SMEM>>>(
        yr, wT + 2 * WST, qkv + 2 * QKVST, (int)TOK, OUTD, DIM, 0, 0, 0, 1.0f);

    // scores = (Q @ K^T) / 32, per batch (no extra rounding; softmax rounds)
    gemm_tf32<false, false><<<dim3(SEQ / 128, SEQ / 128, BSZ), 256, GEMM_SMEM>>>(
        qkv, qkv + QKVST, sc, SEQ, SEQ, OUTD, BQKV, BQKV, SST, 0.03125f);

    softmax_rows<<<BSZ * SEQ, 256>>>(sc);

    // out = A @ (V^T)^T : B operand = V^T [OUT, SEQ] per batch; fp32 out
    gemm_tf32<false, false><<<dim3(OUTD / 128, SEQ / 128, BSZ), 256, GEMM_SMEM>>>(
        sc, qkv + 2 * QKVST, out, SEQ, OUTD, SEQ, SST, BQKV, BQKV, 1.0f);
}

// round 6
// speedup vs baseline: 3.4977x; 1.1701x over previous
#include <cuda_runtime.h>
#include <cuda_bf16.h>
#include <cstdint>
#include <math.h>

// Problem constants
#define BSZ   4
#define SEQ   2048
#define DIM   1024
#define OUTD  1024

// Scratch (__device__ globals; allocation-free). 128B aligned for cp.async.
__device__ __align__(128) float g_qkv[3ull * BSZ * SEQ * OUTD];   // Q | K | V^T planes
__device__ __align__(128) float g_scores[(size_t)BSZ * SEQ * SEQ];
__device__ __align__(128) float g_xr[(size_t)BSZ * SEQ * DIM];
__device__ __align__(128) float g_yr[(size_t)BSZ * SEQ * DIM];
__device__ __align__(128) float g_wT[3ull * OUTD * DIM];

// ---------------------------------------------------------------------------
// Helpers
// ---------------------------------------------------------------------------
__device__ __forceinline__ uint32_t smem_u32(const void* p) {
    uint32_t a;
    asm("{ .reg .u64 t; cvta.to.shared.u64 t, %1; cvt.u32.u64 %0, t; }" : "=r"(a) : "l"(p));
    return a;
}
__device__ __forceinline__ float rn_tf32(float x) {
    uint32_t o;
    asm("cvt.rna.tf32.f32 %0, %1;" : "=r"(o) : "f"(x));
    return __uint_as_float(o);
}
__device__ __forceinline__ void cp16(uint32_t dst, const void* src) {
    asm volatile("cp.async.cg.shared.global [%0], [%1], 16;" :: "r"(dst), "l"(src) : "memory");
}
#define CP_COMMIT() asm volatile("cp.async.commit_group;" ::: "memory")
#define CP_WAIT1()  asm volatile("cp.async.wait_group 1;" ::: "memory")
#define CP_WAIT0()  asm volatile("cp.async.wait_group 0;" ::: "memory")

// Scalar LDS via explicit shared-state-space load (32-bit smem addressing)
__device__ __forceinline__ uint32_t lds32(uint32_t addr) {
    uint32_t v;
    asm volatile("ld.shared.b32 %0, [%1];" : "=r"(v) : "r"(addr));
    return v;
}

// m16n8k8 tf32 MMA (sm_80+; legal on plain sm_100 target)
__device__ __forceinline__ void mma_tf32(float* c, const uint32_t* a, const uint32_t* b) {
    asm volatile(
        "mma.sync.aligned.m16n8k8.row.col.f32.tf32.tf32.f32 "
        "{%0,%1,%2,%3}, {%4,%5,%6,%7}, {%8,%9}, {%0,%1,%2,%3};"
        : "+f"(c[0]), "+f"(c[1]), "+f"(c[2]), "+f"(c[3])
        : "r"(a[0]), "r"(a[1]), "r"(a[2]), "r"(a[3]), "r"(b[0]), "r"(b[1]));
}

// ---------------------------------------------------------------------------
// tf32 tensor GEMM: C = alpha * A * B^T
//   A: [M,K] row-major, B: [N,K] row-major, C: [M,N] row-major.
//   All operands pre-rounded to tf32 (low 13 mantissa bits zero).
// CTA tile 128x128, K-chunk 32, 256 threads (8 warps, 2x4, warp tile 64x32).
// SMEM rows padded to 36 floats -> conflict-free fragment LDS.
// __launch_bounds__(256, 2): cap regs at 128 so 2 CTAs/SM (16 warps) fit.
// ---------------------------------------------------------------------------
#define TK_ 32
#define LDA_ 36                          // padded row stride (floats)
#define LDAB_ (LDA_ * 4)                 // padded row stride (bytes)
#define TILE_F (128 * LDA_)              // floats per operand tile = 4608
#define STAGE_F (2 * TILE_F)             // A+B per stage
#define GEMM_SMEM (2 * STAGE_F * 4)      // 73728 bytes

template <bool ROUND, bool TRANSV>
__global__ __launch_bounds__(256, 2) void gemm_tf32(
    const float* __restrict__ A, const float* __restrict__ B, float* __restrict__ C,
    int M, int N, int K, long sA, long sB, long sC, float alpha)
{
    extern __shared__ float sm[];
    const uint32_t sbase = smem_u32(sm);

    const int tid  = threadIdx.x;
    const int lane = tid & 31;
    const int wid  = tid >> 5;
    const int wr   = wid >> 2;            // warp row 0..1
    const int wc   = wid & 3;             // warp col 0..3
    const int m0   = wr * 64;
    const int n0   = wc * 32;
    const int fr   = lane >> 2;           // fragment row group 0..7
    const int fc   = lane & 3;            // fragment col group 0..3

    const float* Ab = A + (size_t)blockIdx.z * sA;
    const float* Bb = B + (size_t)blockIdx.z * sB;
    float*       Cb = C + (size_t)blockIdx.z * sC;
    const int cRow = blockIdx.y * 128;
    const int cCol = blockIdx.x * 128;

    // Per-warp smem byte offsets (within a stage), hoisted out of the k-loop.
    const uint32_t aOff = (uint32_t)(m0 + fr) * LDAB_ + (uint32_t)fc * 4;
    const uint32_t bOff = (uint32_t)(n0 + fr) * LDAB_ + (uint32_t)fc * 4 + TILE_F * 4;

    float acc[4][4][4];
    #pragma unroll
    for (int i = 0; i < 4; i++)
        #pragma unroll
        for (int j = 0; j < 4; j++)
            #pragma unroll
            for (int v = 0; v < 4; v++) acc[i][j][v] = 0.0f;

    const int NT = K / TK_;

    // Tile loader: 128 rows x 8 x 16B chunks per operand; 4 chunks/thread/operand.
    auto loadTile = [&](int it, int s) {
        const uint32_t aB = sbase + (uint32_t)s * (STAGE_F * 4);
        const uint32_t bB = aB + TILE_F * 4;
        const float* Ag = Ab + (size_t)cRow * K + (size_t)it * TK_;
        const float* Bg = Bb + (size_t)cCol * K + (size_t)it * TK_;
        #pragma unroll
        for (int j = 0; j < 4; j++) {
            const int id = tid + j * 256;        // 0..1023
            const int r = id >> 3, c = id & 7;   // row, 16B chunk
            const uint32_t off = (uint32_t)r * LDAB_ + (uint32_t)c * 16;
            cp16(aB + off, Ag + (size_t)r * K + c * 4);
            cp16(bB + off, Bg + (size_t)r * K + c * 4);
        }
    };

    loadTile(0, 0);
    CP_COMMIT();

    for (int it = 0; it < NT; it++) {
        if (it + 1 < NT) {
            loadTile(it + 1, (it + 1) & 1);
            CP_COMMIT();
            CP_WAIT1();
        } else {
            CP_WAIT0();
        }
        __syncthreads();

        const uint32_t stage = sbase + (uint32_t)(it & 1) * (STAGE_F * 4);
        const uint32_t aBase = stage + aOff;
        const uint32_t bBase = stage + bOff;

        #pragma unroll
        for (int kk = 0; kk < 4; kk++) {
            const uint32_t kb = (uint32_t)kk * 32;   // k0*4 bytes
            uint32_t a[4][4], b[4][2];
            #pragma unroll
            for (int i = 0; i < 4; i++) {
                const uint32_t ap = aBase + (uint32_t)(16 * i) * LDAB_ + kb;
                a[i][0] = lds32(ap);
                a[i][1] = lds32(ap + 8 * LDAB_);
                a[i][2] = lds32(ap + 16);
                a[i][3] = lds32(ap + 8 * LDAB_ + 16);
            }
            #pragma unroll
            for (int j = 0; j < 4; j++) {
                const uint32_t bp = bBase + (uint32_t)(8 * j) * LDAB_ + kb;
                b[j][0] = lds32(bp);
                b[j][1] = lds32(bp + 16);
            }
            #pragma unroll
            for (int i = 0; i < 4; i++)
                #pragma unroll
                for (int j = 0; j < 4; j++)
                    mma_tf32(acc[i][j], a[i], b[j]);
        }
        __syncthreads();
    }

    // Epilogue
    #pragma unroll
    for (int i = 0; i < 4; i++) {
        const int row0 = cRow + m0 + 16 * i + fr;
        #pragma unroll
        for (int j = 0; j < 4; j++) {
            const int col0 = cCol + n0 + 8 * j + 2 * fc;
            float v0 = alpha * acc[i][j][0];
            float v1 = alpha * acc[i][j][1];
            float v2 = alpha * acc[i][j][2];
            float v3 = alpha * acc[i][j][3];
            if (ROUND) { v0 = rn_tf32(v0); v1 = rn_tf32(v1);
                         v2 = rn_tf32(v2); v3 = rn_tf32(v3); }
            if (TRANSV) {
                // Store transposed: out[b][o][s], row -> (b, s), col -> o
                const int b_ = row0 >> 11, s_ = row0 & (SEQ - 1);
                float* o0 = C + (size_t)b_ * OUTD * SEQ + (size_t)col0 * SEQ + s_;
                o0[0]       = v0;
                o0[SEQ]     = v1;
                o0[8]       = v2;     // row0+8, col0
                o0[SEQ + 8] = v3;     // row0+8, col0+1
            } else {
                float2 p0 = make_float2(v0, v1);
                float2 p1 = make_float2(v2, v3);
                *reinterpret_cast<float2*>(Cb + (size_t)row0 * N + col0)       = p0;
                *reinterpret_cast<float2*>(Cb + (size_t)(row0 + 8) * N + col0) = p1;
            }
        }
    }
}

// ---------------------------------------------------------------------------
// Prep: round to tf32 (RN), batched over z (0: x->xr, 1: y->yr); transpose+round W
// ---------------------------------------------------------------------------
__global__ __launch_bounds__(256) void round_tf32_kernel(
    const float4* __restrict__ in0, float4* __restrict__ out0,
    const float4* __restrict__ in1, float4* __restrict__ out1, int n4)
{
    int i = blockIdx.x * 256 + threadIdx.x;
    const float4* in  = blockIdx.z ? in1  : in0;
    float4*       out = blockIdx.z ? out1 : out0;
    if (i < n4) {
        float4 v = in[i];
        v.x = rn_tf32(v.x); v.y = rn_tf32(v.y); v.z = rn_tf32(v.z); v.w = rn_tf32(v.w);
        out[i] = v;
    }
}

__global__ __launch_bounds__(256) void wtrans_kernel(
    const float* __restrict__ w, float* __restrict__ wT)
{
    __shared__ float t[32][33];
    const int p = blockIdx.z;
    const int o0 = blockIdx.x * 32, d0 = blockIdx.y * 32;
    const int tx = threadIdx.x & 31, ty = threadIdx.x >> 5;   // 32 x 8
    const float* wp = w + (size_t)p * DIM * OUTD;
    float* wtp = wT + (size_t)p * OUTD * DIM;
    #pragma unroll
    for (int j = 0; j < 4; j++)
        t[ty + j * 8][tx] = wp[(size_t)(d0 + ty + j * 8) * OUTD + o0 + tx];
    __syncthreads();
    #pragma unroll
    for (int j = 0; j < 4; j++)
        wtp[(size_t)(o0 + ty + j * 8) * DIM + d0 + tx] = rn_tf32(t[tx][ty + j * 8]);
}

// ---------------------------------------------------------------------------
// Row softmax (rows of 2048), output rounded to tf32
// ---------------------------------------------------------------------------
__device__ __forceinline__ float warpReduceMax(float v) {
    #pragma unroll
    for (int o = 16; o > 0; o >>= 1) v = fmaxf(v, __shfl_xor_sync(0xffffffffu, v, o));
    return v;
}
__device__ __forceinline__ float warpReduceSum(float v) {
    #pragma unroll
    for (int o = 16; o > 0; o >>= 1) v += __shfl_xor_sync(0xffffffffu, v, o);
    return v;
}

__global__ __launch_bounds__(256) void softmax_rows(float* __restrict__ S)
{
    const int t = threadIdx.x;
    float4* row = reinterpret_cast<float4*>(S + (size_t)blockIdx.x * SEQ);
    float4 a = row[t];
    float4 b = row[t + 256];

    __shared__ float red[8];

    float m = fmaxf(fmaxf(fmaxf(a.x, a.y), fmaxf(a.z, a.w)),
                    fmaxf(fmaxf(b.x, b.y), fmaxf(b.z, b.w)));
    m = warpReduceMax(m);
    if ((t & 31) == 0) red[t >> 5] = m;
    __syncthreads();
    if (t < 32) {
        float v = (t < 8) ? red[t] : -INFINITY;
        v = warpReduceMax(v);
        if (t == 0) red[0] = v;
    }
    __syncthreads();
    m = red[0];
    __syncthreads();

    a.x = expf(a.x - m); a.y = expf(a.y - m); a.z = expf(a.z - m); a.w = expf(a.w - m);
    b.x = expf(b.x - m); b.y = expf(b.y - m); b.z = expf(b.z - m); b.w = expf(b.w - m);
    float s = a.x + a.y + a.z + a.w + b.x + b.y + b.z + b.w;
    s = warpReduceSum(s);
    if ((t & 31) == 0) red[t >> 5] = s;
    __syncthreads();
    if (t < 32) {
        float v = (t < 8) ? red[t] : 0.0f;
        v = warpReduceSum(v);
        if (t == 0) red[0] = v;
    }
    __syncthreads();
    const float inv = 1.0f / red[0];

    a.x = rn_tf32(a.x * inv); a.y = rn_tf32(a.y * inv);
    a.z = rn_tf32(a.z * inv); a.w = rn_tf32(a.w * inv);
    b.x = rn_tf32(b.x * inv); b.y = rn_tf32(b.y * inv);
    b.z = rn_tf32(b.z * inv); b.w = rn_tf32(b.w * inv);
    row[t] = a;
    row[t + 256] = b;
}

// ---------------------------------------------------------------------------
// Launch
// ---------------------------------------------------------------------------
extern "C" void kernel_launch(void* const* d_in, const int* in_sizes, int n_in,
                              void* d_out, int out_size)
{
    const float* x = (const float*)d_in[0];   // [B,S,D]
    const float* y = (const float*)d_in[1];   // [B,S,D]
    const float* w = (const float*)d_in[2];   // [3,D,OUT]
    float* out = (float*)d_out;               // [B,S,OUT]

    float *qkv, *sc, *xr, *yr, *wT;
    cudaGetSymbolAddress((void**)&qkv, g_qkv);
    cudaGetSymbolAddress((void**)&sc,  g_scores);
    cudaGetSymbolAddress((void**)&xr,  g_xr);
    cudaGetSymbolAddress((void**)&yr,  g_yr);
    cudaGetSymbolAddress((void**)&wT,  g_wT);

    cudaFuncSetAttribute(gemm_tf32<true,  false>, cudaFuncAttributeMaxDynamicSharedMemorySize, GEMM_SMEM);
    cudaFuncSetAttribute(gemm_tf32<false, false>, cudaFuncAttributeMaxDynamicSharedMemorySize, GEMM_SMEM);
    cudaFuncSetAttribute(gemm_tf32<true,  true >, cudaFuncAttributeMaxDynamicSharedMemorySize, GEMM_SMEM);

    const long TOK   = (long)BSZ * SEQ;        // 8192
    const long QKVST = TOK * OUTD;             // per-plane
    const long WST   = (long)DIM * OUTD;
    const long SST   = (long)SEQ * SEQ;
    const long BQKV  = (long)SEQ * OUTD;

    // Prep: round inputs (x,y batched over z), transpose+round W
    const int n4 = (int)(TOK * DIM / 4);
    round_tf32_kernel<<<dim3((n4 + 255) / 256, 1, 2), 256>>>(
        (const float4*)x, (float4*)xr, (const float4*)y, (float4*)yr, n4);
    wtrans_kernel<<<dim3(OUTD / 32, DIM / 32, 3), 256>>>(w, wT);

    // Q = xr @ W0^T', K = xr @ W1^T'  (z over weight planes), rounded outputs
    gemm_tf32<true, false><<<dim3(OUTD / 128, TOK / 128, 2), 256, GEMM_SMEM>>>(
        xr, wT, qkv, (int)TOK, OUTD, DIM, 0, WST, QKVST, 1.0f);

    // V^T = (yr @ W2^T')^T  (transposed, rounded store into plane 2)
    gemm_tf32<true, true><<<dim3(OUTD / 128, TOK / 128, 1), 256, GEMM_SMEM>>>(
        yr, wT + 2 * WST, qkv + 2 * QKVST, (int)TOK, OUTD, DIM, 0, 0, 0, 1.0f);

    // scores = (Q @ K^T) / 32, per batch (no extra rounding; softmax rounds)
    gemm_tf32<false, false><<<dim3(SEQ / 128, SEQ / 128, BSZ), 256, GEMM_SMEM>>>(
        qkv, qkv + QKVST, sc, SEQ, SEQ, OUTD, BQKV, BQKV, SST, 0.03125f);

    softmax_rows<<<BSZ * SEQ, 256>>>(sc);

    // out = A @ (V^T)^T : B operand = V^T [OUT, SEQ] per batch; fp32 out
    gemm_tf32<false, false><<<dim3(OUTD / 128, SEQ / 128, BSZ), 256, GEMM_SMEM>>>(
        sc, qkv + 2 * QKVST, out, SEQ, OUTD, SEQ, SST, BQKV, BQKV, 1.0f);
}

// round 7
// speedup vs baseline: 3.9507x; 1.1295x over previous
#include <cuda_runtime.h>
#include <cuda_bf16.h>
#include <cstdint>
#include <math.h>

// Problem constants
#define BSZ   4
#define SEQ   2048
#define DIM   1024
#define OUTD  1024

// Scratch (__device__ globals; allocation-free). 128B aligned for cp.async.
__device__ __align__(128) float g_qkv[3ull * BSZ * SEQ * OUTD];   // Q | K | V^T planes
__device__ __align__(128) float g_scores[(size_t)BSZ * SEQ * SEQ];
__device__ __align__(128) float g_xr[(size_t)BSZ * SEQ * DIM];
__device__ __align__(128) float g_yr[(size_t)BSZ * SEQ * DIM];
__device__ __align__(128) float g_wT[3ull * OUTD * DIM];

// ---------------------------------------------------------------------------
// Helpers
// ---------------------------------------------------------------------------
__device__ __forceinline__ uint32_t smem_u32(const void* p) {
    uint32_t a;
    asm("{ .reg .u64 t; cvta.to.shared.u64 t, %1; cvt.u32.u64 %0, t; }" : "=r"(a) : "l"(p));
    return a;
}
__device__ __forceinline__ float rn_tf32(float x) {
    uint32_t o;
    asm("cvt.rna.tf32.f32 %0, %1;" : "=r"(o) : "f"(x));
    return __uint_as_float(o);
}
__device__ __forceinline__ void cp16(uint32_t dst, const void* src) {
    asm volatile("cp.async.cg.shared.global [%0], [%1], 16;" :: "r"(dst), "l"(src) : "memory");
}
#define CP_COMMIT() asm volatile("cp.async.commit_group;" ::: "memory")
#define CP_WAIT1()  asm volatile("cp.async.wait_group 1;" ::: "memory")
#define CP_WAIT0()  asm volatile("cp.async.wait_group 0;" ::: "memory")

// ldmatrix x4: four 8x8 b16 matrices == four 8x4 fp32 blocks; lane l of each
// matrix receives the fp32 at (row=l/4, col=l%4) -> exactly the tf32 fragment map.
__device__ __forceinline__ void ldsm_x4(uint32_t* r, uint32_t addr) {
    asm volatile("ldmatrix.sync.aligned.m8n8.x4.shared.b16 {%0,%1,%2,%3}, [%4];"
                 : "=r"(r[0]), "=r"(r[1]), "=r"(r[2]), "=r"(r[3]) : "r"(addr));
}

// m16n8k8 tf32 MMA (sm_80+; legal on plain sm_100 target)
__device__ __forceinline__ void mma_tf32(float* c, const uint32_t* a, const uint32_t* b) {
    asm volatile(
        "mma.sync.aligned.m16n8k8.row.col.f32.tf32.tf32.f32 "
        "{%0,%1,%2,%3}, {%4,%5,%6,%7}, {%8,%9}, {%0,%1,%2,%3};"
        : "+f"(c[0]), "+f"(c[1]), "+f"(c[2]), "+f"(c[3])
        : "r"(a[0]), "r"(a[1]), "r"(a[2]), "r"(a[3]), "r"(b[0]), "r"(b[1]));
}

// ---------------------------------------------------------------------------
// tf32 tensor GEMM: C = alpha * A * B^T
//   A: [M,K] row-major, B: [N,K] row-major, C: [M,N] row-major.
//   All operands pre-rounded to tf32 (low 13 mantissa bits zero).
// CTA tile 128x128, K-chunk 32, 256 threads (8 warps, 2x4, warp tile 64x32).
// SMEM rows padded to 36 floats: conflict-free for both cp.async stores and
// ldmatrix reads (row stride 144B -> banks 4r..4r+3, all 32 banks across 8 rows).
// __launch_bounds__(256, 2): 2 CTAs/SM (16 warps).
// ---------------------------------------------------------------------------
#define TK_ 32
#define LDA_ 36                          // padded row stride (floats)
#define LDAB_ (LDA_ * 4)                 // padded row stride (bytes)
#define TILE_F (128 * LDA_)              // floats per operand tile = 4608
#define STAGE_F (2 * TILE_F)             // A+B per stage
#define GEMM_SMEM (2 * STAGE_F * 4)      // 73728 bytes

template <bool ROUND, bool TRANSV>
__global__ __launch_bounds__(256, 2) void gemm_tf32(
    const float* __restrict__ A, const float* __restrict__ B, float* __restrict__ C,
    int M, int N, int K, long sA, long sB, long sC, float alpha)
{
    extern __shared__ float sm[];
    const uint32_t sbase = smem_u32(sm);

    const int tid  = threadIdx.x;
    const int lane = tid & 31;
    const int wid  = tid >> 5;
    const int wr   = wid >> 2;            // warp row 0..1
    const int wc   = wid & 3;             // warp col 0..3
    const int m0   = wr * 64;
    const int n0   = wc * 32;
    const int fr   = lane >> 2;           // fragment row group 0..7
    const int fc   = lane & 3;            // fragment col group 0..3

    const float* Ab = A + (size_t)blockIdx.z * sA;
    const float* Bb = B + (size_t)blockIdx.z * sB;
    float*       Cb = C + (size_t)blockIdx.z * sC;
    const int cRow = blockIdx.y * 128;
    const int cCol = blockIdx.x * 128;

    // Per-thread ldmatrix base offsets (byte offsets within a stage).
    // A x4 (per 16-row block i): matrices = {rows 0-7 k0, rows 8-15 k0,
    //   rows 0-7 k0+4, rows 8-15 k0+4} -> row sel = lane&15, col sel = (lane>>4)*16.
    const uint32_t aLdsm = (uint32_t)(m0 + (lane & 15)) * LDAB_ + (uint32_t)(lane >> 4) * 16;
    // B x4 (per pair of 8-row n-blocks j, j+1): matrices = {nj k0, nj k0+4,
    //   nj+8 k0, nj+8 k0+4} -> row = n0 + (lane&7) + (lane>=16)*8, col = ((lane>>3)&1)*16.
    const uint32_t bLdsm = (uint32_t)(n0 + (lane & 7) + ((lane >> 4) << 3)) * LDAB_
                         + (uint32_t)((lane >> 3) & 1) * 16 + TILE_F * 4;

    float acc[4][4][4];
    #pragma unroll
    for (int i = 0; i < 4; i++)
        #pragma unroll
        for (int j = 0; j < 4; j++)
            #pragma unroll
            for (int v = 0; v < 4; v++) acc[i][j][v] = 0.0f;

    const int NT = K / TK_;

    // Tile loader: 128 rows x 8 x 16B chunks per operand; 4 chunks/thread/operand.
    auto loadTile = [&](int it, int s) {
        const uint32_t aB = sbase + (uint32_t)s * (STAGE_F * 4);
        const uint32_t bB = aB + TILE_F * 4;
        const float* Ag = Ab + (size_t)cRow * K + (size_t)it * TK_;
        const float* Bg = Bb + (size_t)cCol * K + (size_t)it * TK_;
        #pragma unroll
        for (int j = 0; j < 4; j++) {
            const int id = tid + j * 256;        // 0..1023
            const int r = id >> 3, c = id & 7;   // row, 16B chunk
            const uint32_t off = (uint32_t)r * LDAB_ + (uint32_t)c * 16;
            cp16(aB + off, Ag + (size_t)r * K + c * 4);
            cp16(bB + off, Bg + (size_t)r * K + c * 4);
        }
    };

    loadTile(0, 0);
    CP_COMMIT();

    for (int it = 0; it < NT; it++) {
        if (it + 1 < NT) {
            loadTile(it + 1, (it + 1) & 1);
            CP_COMMIT();
            CP_WAIT1();
        } else {
            CP_WAIT0();
        }
        __syncthreads();

        const uint32_t stage = sbase + (uint32_t)(it & 1) * (STAGE_F * 4);
        const uint32_t aBase = stage + aLdsm;
        const uint32_t bBase = stage + bLdsm;

        #pragma unroll
        for (int kk = 0; kk < 4; kk++) {
            const uint32_t kb = (uint32_t)kk * 32;   // k0*4 bytes
            uint32_t a[4][4], b[4][2];
            #pragma unroll
            for (int i = 0; i < 4; i++)
                ldsm_x4(a[i], aBase + (uint32_t)(16 * i) * LDAB_ + kb);
            ldsm_x4(&b[0][0], bBase + kb);                         // n-blocks 0,1
            ldsm_x4(&b[2][0], bBase + 16 * LDAB_ + kb);            // n-blocks 2,3
            #pragma unroll
            for (int i = 0; i < 4; i++)
                #pragma unroll
                for (int j = 0; j < 4; j++)
                    mma_tf32(acc[i][j], a[i], b[j]);
        }
        __syncthreads();
    }

    // Epilogue
    #pragma unroll
    for (int i = 0; i < 4; i++) {
        const int row0 = cRow + m0 + 16 * i + fr;
        #pragma unroll
        for (int j = 0; j < 4; j++) {
            const int col0 = cCol + n0 + 8 * j + 2 * fc;
            float v0 = alpha * acc[i][j][0];
            float v1 = alpha * acc[i][j][1];
            float v2 = alpha * acc[i][j][2];
            float v3 = alpha * acc[i][j][3];
            if (ROUND) { v0 = rn_tf32(v0); v1 = rn_tf32(v1);
                         v2 = rn_tf32(v2); v3 = rn_tf32(v3); }
            if (TRANSV) {
                // Store transposed: out[b][o][s], row -> (b, s), col -> o
                const int b_ = row0 >> 11, s_ = row0 & (SEQ - 1);
                float* o0 = C + (size_t)b_ * OUTD * SEQ + (size_t)col0 * SEQ + s_;
                o0[0]       = v0;
                o0[SEQ]     = v1;
                o0[8]       = v2;     // row0+8, col0
                o0[SEQ + 8] = v3;     // row0+8, col0+1
            } else {
                float2 p0 = make_float2(v0, v1);
                float2 p1 = make_float2(v2, v3);
                *reinterpret_cast<float2*>(Cb + (size_t)row0 * N + col0)       = p0;
                *reinterpret_cast<float2*>(Cb + (size_t)(row0 + 8) * N + col0) = p1;
            }
        }
    }
}

// ---------------------------------------------------------------------------
// Prep: round to tf32 (RN), batched over z (0: x->xr, 1: y->yr); transpose+round W
// ---------------------------------------------------------------------------
__global__ __launch_bounds__(256) void round_tf32_kernel(
    const float4* __restrict__ in0, float4* __restrict__ out0,
    const float4* __restrict__ in1, float4* __restrict__ out1, int n4)
{
    int i = blockIdx.x * 256 + threadIdx.x;
    const float4* in  = blockIdx.z ? in1  : in0;
    float4*       out = blockIdx.z ? out1 : out0;
    if (i < n4) {
        float4 v = in[i];
        v.x = rn_tf32(v.x); v.y = rn_tf32(v.y); v.z = rn_tf32(v.z); v.w = rn_tf32(v.w);
        out[i] = v;
    }
}

__global__ __launch_bounds__(256) void wtrans_kernel(
    const float* __restrict__ w, float* __restrict__ wT)
{
    __shared__ float t[32][33];
    const int p = blockIdx.z;
    const int o0 = blockIdx.x * 32, d0 = blockIdx.y * 32;
    const int tx = threadIdx.x & 31, ty = threadIdx.x >> 5;   // 32 x 8
    const float* wp = w + (size_t)p * DIM * OUTD;
    float* wtp = wT + (size_t)p * OUTD * DIM;
    #pragma unroll
    for (int j = 0; j < 4; j++)
        t[ty + j * 8][tx] = wp[(size_t)(d0 + ty + j * 8) * OUTD + o0 + tx];
    __syncthreads();
    #pragma unroll
    for (int j = 0; j < 4; j++)
        wtp[(size_t)(o0 + ty + j * 8) * DIM + d0 + tx] = rn_tf32(t[tx][ty + j * 8]);
}

// ---------------------------------------------------------------------------
// Row softmax (rows of 2048), output rounded to tf32
// ---------------------------------------------------------------------------
__device__ __forceinline__ float warpReduceMax(float v) {
    #pragma unroll
    for (int o = 16; o > 0; o >>= 1) v = fmaxf(v, __shfl_xor_sync(0xffffffffu, v, o));
    return v;
}
__device__ __forceinline__ float warpReduceSum(float v) {
    #pragma unroll
    for (int o = 16; o > 0; o >>= 1) v += __shfl_xor_sync(0xffffffffu, v, o);
    return v;
}

__global__ __launch_bounds__(256) void softmax_rows(float* __restrict__ S)
{
    const int t = threadIdx.x;
    float4* row = reinterpret_cast<float4*>(S + (size_t)blockIdx.x * SEQ);
    float4 a = row[t];
    float4 b = row[t + 256];

    __shared__ float red[8];

    float m = fmaxf(fmaxf(fmaxf(a.x, a.y), fmaxf(a.z, a.w)),
                    fmaxf(fmaxf(b.x, b.y), fmaxf(b.z, b.w)));
    m = warpReduceMax(m);
    if ((t & 31) == 0) red[t >> 5] = m;
    __syncthreads();
    if (t < 32) {
        float v = (t < 8) ? red[t] : -INFINITY;
        v = warpReduceMax(v);
        if (t == 0) red[0] = v;
    }
    __syncthreads();
    m = red[0];
    __syncthreads();

    a.x = expf(a.x - m); a.y = expf(a.y - m); a.z = expf(a.z - m); a.w = expf(a.w - m);
    b.x = expf(b.x - m); b.y = expf(b.y - m); b.z = expf(b.z - m); b.w = expf(b.w - m);
    float s = a.x + a.y + a.z + a.w + b.x + b.y + b.z + b.w;
    s = warpReduceSum(s);
    if ((t & 31) == 0) red[t >> 5] = s;
    __syncthreads();
    if (t < 32) {
        float v = (t < 8) ? red[t] : 0.0f;
        v = warpReduceSum(v);
        if (t == 0) red[0] = v;
    }
    __syncthreads();
    const float inv = 1.0f / red[0];

    a.x = rn_tf32(a.x * inv); a.y = rn_tf32(a.y * inv);
    a.z = rn_tf32(a.z * inv); a.w = rn_tf32(a.w * inv);
    b.x = rn_tf32(b.x * inv); b.y = rn_tf32(b.y * inv);
    b.z = rn_tf32(b.z * inv); b.w = rn_tf32(b.w * inv);
    row[t] = a;
    row[t + 256] = b;
}

// ---------------------------------------------------------------------------
// Launch
// ---------------------------------------------------------------------------
extern "C" void kernel_launch(void* const* d_in, const int* in_sizes, int n_in,
                              void* d_out, int out_size)
{
    const float* x = (const float*)d_in[0];   // [B,S,D]
    const float* y = (const float*)d_in[1];   // [B,S,D]
    const float* w = (const float*)d_in[2];   // [3,D,OUT]
    float* out = (float*)d_out;               // [B,S,OUT]

    float *qkv, *sc, *xr, *yr, *wT;
    cudaGetSymbolAddress((void**)&qkv, g_qkv);
    cudaGetSymbolAddress((void**)&sc,  g_scores);
    cudaGetSymbolAddress((void**)&xr,  g_xr);
    cudaGetSymbolAddress((void**)&yr,  g_yr);
    cudaGetSymbolAddress((void**)&wT,  g_wT);

    cudaFuncSetAttribute(gemm_tf32<true,  false>, cudaFuncAttributeMaxDynamicSharedMemorySize, GEMM_SMEM);
    cudaFuncSetAttribute(gemm_tf32<false, false>, cudaFuncAttributeMaxDynamicSharedMemorySize, GEMM_SMEM);
    cudaFuncSetAttribute(gemm_tf32<true,  true >, cudaFuncAttributeMaxDynamicSharedMemorySize, GEMM_SMEM);

    const long TOK   = (long)BSZ * SEQ;        // 8192
    const long QKVST = TOK * OUTD;             // per-plane
    const long WST   = (long)DIM * OUTD;
    const long SST   = (long)SEQ * SEQ;
    const long BQKV  = (long)SEQ * OUTD;

    // Prep: round inputs (x,y batched over z), transpose+round W
    const int n4 = (int)(TOK * DIM / 4);
    round_tf32_kernel<<<dim3((n4 + 255) / 256, 1, 2), 256>>>(
        (const float4*)x, (float4*)xr, (const float4*)y, (float4*)yr, n4);
    wtrans_kernel<<<dim3(OUTD / 32, DIM / 32, 3), 256>>>(w, wT);

    // Q = xr @ W0^T', K = xr @ W1^T'  (z over weight planes), rounded outputs
    gemm_tf32<true, false><<<dim3(OUTD / 128, TOK / 128, 2), 256, GEMM_SMEM>>>(
        xr, wT, qkv, (int)TOK, OUTD, DIM, 0, WST, QKVST, 1.0f);

    // V^T = (yr @ W2^T')^T  (transposed, rounded store into plane 2)
    gemm_tf32<true, true><<<dim3(OUTD / 128, TOK / 128, 1), 256, GEMM_SMEM>>>(
        yr, wT + 2 * WST, qkv + 2 * QKVST, (int)TOK, OUTD, DIM, 0, 0, 0, 1.0f);

    // scores = (Q @ K^T) / 32, per batch (no extra rounding; softmax rounds)
    gemm_tf32<false, false><<<dim3(SEQ / 128, SEQ / 128, BSZ), 256, GEMM_SMEM>>>(
        qkv, qkv + QKVST, sc, SEQ, SEQ, OUTD, BQKV, BQKV, SST, 0.03125f);

    softmax_rows<<<BSZ * SEQ, 256>>>(sc);

    // out = A @ (V^T)^T : B operand = V^T [OUT, SEQ] per batch; fp32 out
    gemm_tf32<false, false><<<dim3(OUTD / 128, SEQ / 128, BSZ), 256, GEMM_SMEM>>>(
        sc, qkv + 2 * QKVST, out, SEQ, OUTD, SEQ, SST, BQKV, BQKV, 1.0f);
}

// round 8
// speedup vs baseline: 4.0530x; 1.0259x over previous
#include <cuda_runtime.h>
#include <cuda_bf16.h>
#include <cstdint>
#include <math.h>

// Problem constants
#define BSZ   4
#define SEQ   2048
#define DIM   1024
#define OUTD  1024

// Scratch (__device__ globals; allocation-free). 128B aligned for cp.async.
__device__ __align__(128) float g_qkv[3ull * BSZ * SEQ * OUTD];   // Q | K | V^T planes
__device__ __align__(128) float g_scores[(size_t)BSZ * SEQ * SEQ];
__device__ __align__(128) float g_xr[(size_t)BSZ * SEQ * DIM];
__device__ __align__(128) float g_yr[(size_t)BSZ * SEQ * DIM];
__device__ __align__(128) float g_wT[3ull * OUTD * DIM];

// ---------------------------------------------------------------------------
// Helpers
// ---------------------------------------------------------------------------
__device__ __forceinline__ uint32_t smem_u32(const void* p) {
    uint32_t a;
    asm("{ .reg .u64 t; cvta.to.shared.u64 t, %1; cvt.u32.u64 %0, t; }" : "=r"(a) : "l"(p));
    return a;
}
__device__ __forceinline__ float rn_tf32(float x) {
    uint32_t o;
    asm("cvt.rna.tf32.f32 %0, %1;" : "=r"(o) : "f"(x));
    return __uint_as_float(o);
}
__device__ __forceinline__ void cp16(uint32_t dst, const void* src) {
    asm volatile("cp.async.cg.shared.global [%0], [%1], 16;" :: "r"(dst), "l"(src) : "memory");
}
#define CP_COMMIT() asm volatile("cp.async.commit_group;" ::: "memory")
#define CP_WAIT1()  asm volatile("cp.async.wait_group 1;" ::: "memory")
#define CP_WAIT0()  asm volatile("cp.async.wait_group 0;" ::: "memory")

// ldmatrix x4: four 8x8 b16 matrices == four 8x4 fp32 blocks; lane l of each
// matrix receives the fp32 at (row=l/4, col=l%4) -> exactly the tf32 fragment map.
__device__ __forceinline__ void ldsm_x4(uint32_t* r, uint32_t addr) {
    asm volatile("ldmatrix.sync.aligned.m8n8.x4.shared.b16 {%0,%1,%2,%3}, [%4];"
                 : "=r"(r[0]), "=r"(r[1]), "=r"(r[2]), "=r"(r[3]) : "r"(addr));
}

// m16n8k8 tf32 MMA (sm_80+; legal on plain sm_100 target)
__device__ __forceinline__ void mma_tf32(float* c, const uint32_t* a, const uint32_t* b) {
    asm volatile(
        "mma.sync.aligned.m16n8k8.row.col.f32.tf32.tf32.f32 "
        "{%0,%1,%2,%3}, {%4,%5,%6,%7}, {%8,%9}, {%0,%1,%2,%3};"
        : "+f"(c[0]), "+f"(c[1]), "+f"(c[2]), "+f"(c[3])
        : "r"(a[0]), "r"(a[1]), "r"(a[2]), "r"(a[3]), "r"(b[0]), "r"(b[1]));
}

// ---------------------------------------------------------------------------
// tf32 tensor GEMM: C = alpha * A * B^T
//   A: [M,K] row-major, B: [N,K] row-major, C: [M,N] row-major.
//   All operands pre-rounded to tf32 (low 13 mantissa bits zero).
// CTA tile 128x128, K-chunk 32, 256 threads (8 warps, 2x4, warp tile 64x32).
// 3-stage cp.async pipeline, ONE __syncthreads per k-iteration:
//   stage written at iter it (tile it+2) == stage read at iter it-1; all warps
//   provably finished that read before passing the iter-it barrier.
// SMEM rows padded to 36 floats: conflict-free for cp.async stores + ldmatrix.
// __launch_bounds__(256, 2): 2 CTAs/SM; smem 2x108KB = 216KB <= 228KB/SM.
// ---------------------------------------------------------------------------
#define TK_ 32
#define LDA_ 36                          // padded row stride (floats)
#define LDAB_ (LDA_ * 4)                 // padded row stride (bytes)
#define TILE_F (128 * LDA_)              // floats per operand tile = 4608
#define STAGE_F (2 * TILE_F)             // A+B per stage
#define NSTAGE 3
#define GEMM_SMEM (NSTAGE * STAGE_F * 4) // 110592 bytes

template <bool ROUND, bool TRANSV>
__global__ __launch_bounds__(256, 2) void gemm_tf32(
    const float* __restrict__ A, const float* __restrict__ B, float* __restrict__ C,
    int M, int N, int K, long sA, long sB, long sC, float alpha)
{
    extern __shared__ float sm[];
    const uint32_t sbase = smem_u32(sm);

    const int tid  = threadIdx.x;
    const int lane = tid & 31;
    const int wid  = tid >> 5;
    const int wr   = wid >> 2;            // warp row 0..1
    const int wc   = wid & 3;             // warp col 0..3
    const int m0   = wr * 64;
    const int n0   = wc * 32;
    const int fr   = lane >> 2;           // fragment row group 0..7
    const int fc   = lane & 3;            // fragment col group 0..3

    const float* Ab = A + (size_t)blockIdx.z * sA;
    const float* Bb = B + (size_t)blockIdx.z * sB;
    float*       Cb = C + (size_t)blockIdx.z * sC;
    const int cRow = blockIdx.y * 128;
    const int cCol = blockIdx.x * 128;

    // Per-thread ldmatrix base offsets (byte offsets within a stage).
    const uint32_t aLdsm = (uint32_t)(m0 + (lane & 15)) * LDAB_ + (uint32_t)(lane >> 4) * 16;
    const uint32_t bLdsm = (uint32_t)(n0 + (lane & 7) + ((lane >> 4) << 3)) * LDAB_
                         + (uint32_t)((lane >> 3) & 1) * 16 + TILE_F * 4;

    float acc[4][4][4];
    #pragma unroll
    for (int i = 0; i < 4; i++)
        #pragma unroll
        for (int j = 0; j < 4; j++)
            #pragma unroll
            for (int v = 0; v < 4; v++) acc[i][j][v] = 0.0f;

    const int NT = K / TK_;

    // Tile loader: 128 rows x 8 x 16B chunks per operand; 4 chunks/thread/operand.
    auto loadTile = [&](int it, int s) {
        const uint32_t aB = sbase + (uint32_t)s * (STAGE_F * 4);
        const uint32_t bB = aB + TILE_F * 4;
        const float* Ag = Ab + (size_t)cRow * K + (size_t)it * TK_;
        const float* Bg = Bb + (size_t)cCol * K + (size_t)it * TK_;
        #pragma unroll
        for (int j = 0; j < 4; j++) {
            const int id = tid + j * 256;        // 0..1023
            const int r = id >> 3, c = id & 7;   // row, 16B chunk
            const uint32_t off = (uint32_t)r * LDAB_ + (uint32_t)c * 16;
            cp16(aB + off, Ag + (size_t)r * K + c * 4);
            cp16(bB + off, Bg + (size_t)r * K + c * 4);
        }
    };

    // Prologue: tiles 0 and 1 in flight.
    loadTile(0, 0);
    CP_COMMIT();
    if (NT > 1) { loadTile(1, 1); CP_COMMIT(); }

    int stage = 0;
    for (int it = 0; it < NT; it++) {
        if (it == NT - 1) { CP_WAIT0(); } else { CP_WAIT1(); }
        __syncthreads();   // tile it visible to all; stage (it-1)%3 free for reuse

        if (it + 2 < NT) {
            int ws = stage + 2; if (ws >= NSTAGE) ws -= NSTAGE;
            loadTile(it + 2, ws);
            CP_COMMIT();
        }

        const uint32_t stg = sbase + (uint32_t)stage * (STAGE_F * 4);
        const uint32_t aBase = stg + aLdsm;
        const uint32_t bBase = stg + bLdsm;

        #pragma unroll
        for (int kk = 0; kk < 4; kk++) {
            const uint32_t kb = (uint32_t)kk * 32;   // k0*4 bytes
            uint32_t a[4][4], b[4][2];
            #pragma unroll
            for (int i = 0; i < 4; i++)
                ldsm_x4(a[i], aBase + (uint32_t)(16 * i) * LDAB_ + kb);
            ldsm_x4(&b[0][0], bBase + kb);                         // n-blocks 0,1
            ldsm_x4(&b[2][0], bBase + 16 * LDAB_ + kb);            // n-blocks 2,3
            #pragma unroll
            for (int i = 0; i < 4; i++)
                #pragma unroll
                for (int j = 0; j < 4; j++)
                    mma_tf32(acc[i][j], a[i], b[j]);
        }

        if (++stage >= NSTAGE) stage = 0;
    }

    // Epilogue
    #pragma unroll
    for (int i = 0; i < 4; i++) {
        const int row0 = cRow + m0 + 16 * i + fr;
        #pragma unroll
        for (int j = 0; j < 4; j++) {
            const int col0 = cCol + n0 + 8 * j + 2 * fc;
            float v0 = alpha * acc[i][j][0];
            float v1 = alpha * acc[i][j][1];
            float v2 = alpha * acc[i][j][2];
            float v3 = alpha * acc[i][j][3];
            if (ROUND) { v0 = rn_tf32(v0); v1 = rn_tf32(v1);
                         v2 = rn_tf32(v2); v3 = rn_tf32(v3); }
            if (TRANSV) {
                // Store transposed: out[b][o][s], row -> (b, s), col -> o
                const int b_ = row0 >> 11, s_ = row0 & (SEQ - 1);
                float* o0 = C + (size_t)b_ * OUTD * SEQ + (size_t)col0 * SEQ + s_;
                o0[0]       = v0;
                o0[SEQ]     = v1;
                o0[8]       = v2;     // row0+8, col0
                o0[SEQ + 8] = v3;     // row0+8, col0+1
            } else {
                float2 p0 = make_float2(v0, v1);
                float2 p1 = make_float2(v2, v3);
                *reinterpret_cast<float2*>(Cb + (size_t)row0 * N + col0)       = p0;
                *reinterpret_cast<float2*>(Cb + (size_t)(row0 + 8) * N + col0) = p1;
            }
        }
    }
}

// ---------------------------------------------------------------------------
// Prep: round to tf32 (RN), batched over z (0: x->xr, 1: y->yr); transpose+round W
// ---------------------------------------------------------------------------
__global__ __launch_bounds__(256) void round_tf32_kernel(
    const float4* __restrict__ in0, float4* __restrict__ out0,
    const float4* __restrict__ in1, float4* __restrict__ out1, int n4)
{
    int i = blockIdx.x * 256 + threadIdx.x;
    const float4* in  = blockIdx.z ? in1  : in0;
    float4*       out = blockIdx.z ? out1 : out0;
    if (i < n4) {
        float4 v = in[i];
        v.x = rn_tf32(v.x); v.y = rn_tf32(v.y); v.z = rn_tf32(v.z); v.w = rn_tf32(v.w);
        out[i] = v;
    }
}

__global__ __launch_bounds__(256) void wtrans_kernel(
    const float* __restrict__ w, float* __restrict__ wT)
{
    __shared__ float t[32][33];
    const int p = blockIdx.z;
    const int o0 = blockIdx.x * 32, d0 = blockIdx.y * 32;
    const int tx = threadIdx.x & 31, ty = threadIdx.x >> 5;   // 32 x 8
    const float* wp = w + (size_t)p * DIM * OUTD;
    float* wtp = wT + (size_t)p * OUTD * DIM;
    #pragma unroll
    for (int j = 0; j < 4; j++)
        t[ty + j * 8][tx] = wp[(size_t)(d0 + ty + j * 8) * OUTD + o0 + tx];
    __syncthreads();
    #pragma unroll
    for (int j = 0; j < 4; j++)
        wtp[(size_t)(o0 + ty + j * 8) * DIM + d0 + tx] = rn_tf32(t[tx][ty + j * 8]);
}

// ---------------------------------------------------------------------------
// Row softmax (rows of 2048), output rounded to tf32
// ---------------------------------------------------------------------------
__device__ __forceinline__ float warpReduceMax(float v) {
    #pragma unroll
    for (int o = 16; o > 0; o >>= 1) v = fmaxf(v, __shfl_xor_sync(0xffffffffu, v, o));
    return v;
}
__device__ __forceinline__ float warpReduceSum(float v) {
    #pragma unroll
    for (int o = 16; o > 0; o >>= 1) v += __shfl_xor_sync(0xffffffffu, v, o);
    return v;
}

__global__ __launch_bounds__(256) void softmax_rows(float* __restrict__ S)
{
    const int t = threadIdx.x;
    float4* row = reinterpret_cast<float4*>(S + (size_t)blockIdx.x * SEQ);
    float4 a = row[t];
    float4 b = row[t + 256];

    __shared__ float red[8];

    float m = fmaxf(fmaxf(fmaxf(a.x, a.y), fmaxf(a.z, a.w)),
                    fmaxf(fmaxf(b.x, b.y), fmaxf(b.z, b.w)));
    m = warpReduceMax(m);
    if ((t & 31) == 0) red[t >> 5] = m;
    __syncthreads();
    if (t < 32) {
        float v = (t < 8) ? red[t] : -INFINITY;
        v = warpReduceMax(v);
        if (t == 0) red[0] = v;
    }
    __syncthreads();
    m = red[0];
    __syncthreads();

    a.x = expf(a.x - m); a.y = expf(a.y - m); a.z = expf(a.z - m); a.w = expf(a.w - m);
    b.x = expf(b.x - m); b.y = expf(b.y - m); b.z = expf(b.z - m); b.w = expf(b.w - m);
    float s = a.x + a.y + a.z + a.w + b.x + b.y + b.z + b.w;
    s = warpReduceSum(s);
    if ((t & 31) == 0) red[t >> 5] = s;
    __syncthreads();
    if (t < 32) {
        float v = (t < 8) ? red[t] : 0.0f;
        v = warpReduceSum(v);
        if (t == 0) red[0] = v;
    }
    __syncthreads();
    const float inv = 1.0f / red[0];

    a.x = rn_tf32(a.x * inv); a.y = rn_tf32(a.y * inv);
    a.z = rn_tf32(a.z * inv); a.w = rn_tf32(a.w * inv);
    b.x = rn_tf32(b.x * inv); b.y = rn_tf32(b.y * inv);
    b.z = rn_tf32(b.z * inv); b.w = rn_tf32(b.w * inv);
    row[t] = a;
    row[t + 256] = b;
}

// ---------------------------------------------------------------------------
// Launch
// ---------------------------------------------------------------------------
extern "C" void kernel_launch(void* const* d_in, const int* in_sizes, int n_in,
                              void* d_out, int out_size)
{
    const float* x = (const float*)d_in[0];   // [B,S,D]
    const float* y = (const float*)d_in[1];   // [B,S,D]
    const float* w = (const float*)d_in[2];   // [3,D,OUT]
    float* out = (float*)d_out;               // [B,S,OUT]

    float *qkv, *sc, *xr, *yr, *wT;
    cudaGetSymbolAddress((void**)&qkv, g_qkv);
    cudaGetSymbolAddress((void**)&sc,  g_scores);
    cudaGetSymbolAddress((void**)&xr,  g_xr);
    cudaGetSymbolAddress((void**)&yr,  g_yr);
    cudaGetSymbolAddress((void**)&wT,  g_wT);

    cudaFuncSetAttribute(gemm_tf32<true,  false>, cudaFuncAttributeMaxDynamicSharedMemorySize, GEMM_SMEM);
    cudaFuncSetAttribute(gemm_tf32<false, false>, cudaFuncAttributeMaxDynamicSharedMemorySize, GEMM_SMEM);
    cudaFuncSetAttribute(gemm_tf32<true,  true >, cudaFuncAttributeMaxDynamicSharedMemorySize, GEMM_SMEM);

    const long TOK   = (long)BSZ * SEQ;        // 8192
    const long QKVST = TOK * OUTD;             // per-plane
    const long WST   = (long)DIM * OUTD;
    const long SST   = (long)SEQ * SEQ;
    const long BQKV  = (long)SEQ * OUTD;

    // Prep: round inputs (x,y batched over z), transpose+round W
    const int n4 = (int)(TOK * DIM / 4);
    round_tf32_kernel<<<dim3((n4 + 255) / 256, 1, 2), 256>>>(
        (const float4*)x, (float4*)xr, (const float4*)y, (float4*)yr, n4);
    wtrans_kernel<<<dim3(OUTD / 32, DIM / 32, 3), 256>>>(w, wT);

    // Q = xr @ W0^T', K = xr @ W1^T'  (z over weight planes), rounded outputs
    gemm_tf32<true, false><<<dim3(OUTD / 128, TOK / 128, 2), 256, GEMM_SMEM>>>(
        xr, wT, qkv, (int)TOK, OUTD, DIM, 0, WST, QKVST, 1.0f);

    // V^T = (yr @ W2^T')^T  (transposed, rounded store into plane 2)
    gemm_tf32<true, true><<<dim3(OUTD / 128, TOK / 128, 1), 256, GEMM_SMEM>>>(
        yr, wT + 2 * WST, qkv + 2 * QKVST, (int)TOK, OUTD, DIM, 0, 0, 0, 1.0f);

    // scores = (Q @ K^T) / 32, per batch (no extra rounding; softmax rounds)
    gemm_tf32<false, false><<<dim3(SEQ / 128, SEQ / 128, BSZ), 256, GEMM_SMEM>>>(
        qkv, qkv + QKVST, sc, SEQ, SEQ, OUTD, BQKV, BQKV, SST, 0.03125f);

    softmax_rows<<<BSZ * SEQ, 256>>>(sc);

    // out = A @ (V^T)^T : B operand = V^T [OUT, SEQ] per batch; fp32 out
    gemm_tf32<false, false><<<dim3(OUTD / 128, SEQ / 128, BSZ), 256, GEMM_SMEM>>>(
        sc, qkv + 2 * QKVST, out, SEQ, OUTD, SEQ, SST, BQKV, BQKV, 1.0f);
}